// round 15
// baseline (speedup 1.0000x reference)
#include <cuda_runtime.h>
#include <cuda_fp16.h>
#include <mma.h>
#include <cstdint>

using namespace nvcuda;

// ---------------------------------------------------------------------------
// GCN layer on GB300 (sm_103a): ONE persistent kernel, software grid barriers.
// Architecture = R12 (best measured, 92.6us) with ONE change: h is FP32, so
// the P4 gather has zero fp16->fp32 conversions (it is issue-bound, R10).
//   P0 gemm   : h = xW + b, wmma HMMA (fp16 in, fp32 acc), 32-row tiles
//   P1 hist   : per-row counts; atomicAdd return = rank
//   -- bar0 --
//   P2 scan   : per-256 chunk exclusive scan + arrival-order base claim
//   -- bar1 --
//   P3 scatter: dense CSR pairs (no atomics)
//   -- bar2 --
//   P4 gather : warp-per-row SpMM + fused PReLU (fp32 h)
// Grid sized for guaranteed co-residency (occupancy API). Barrier counters
// are monotonic epochs -> no reset needed across graph replays.
// ---------------------------------------------------------------------------

#define IN_FT   128
#define OUT_FT  64
#define N_CAP   131072
#define E_CAP   1605632

static __device__ float          g_h[(size_t)N_CAP * OUT_FT];  // 25.6 MB fp32
static __device__ int            g_cnt[N_CAP + 2];   // zero at entry (P2 resets)
static __device__ int2           g_rowseg[N_CAP];    // {start, count}
static __device__ int            g_ebase;            // arrival-order allocator
static __device__ unsigned short g_rank[E_CAP];
static __device__ int2           g_pairs[E_CAP];
static __device__ unsigned       g_barCnt[4];        // monotonic
static __device__ unsigned       g_barRel[4];        // monotonic

// ---- epoch grid barrier (monotonic; safe across graph replays) -------------
__device__ __forceinline__ void grid_barrier(int id, unsigned nb) {
    __syncthreads();
    if (threadIdx.x == 0) {
        __threadfence();
        const unsigned t     = atomicAdd(&g_barCnt[id], 1u);
        const unsigned epoch = t / nb + 1u;
        if ((t % nb) == nb - 1u) atomicAdd(&g_barRel[id], 1u);
        while (*((volatile unsigned*)&g_barRel[id]) < epoch) __nanosleep(64);
    }
    __syncthreads();
}

#define XS_PITCH 136
#define WS_PITCH 72
#define OS_PITCH 68
#define XS_BYTES (32 * XS_PITCH * 2)     // 8704 (== 32*68*4; Os overlays Xs)
#define WS_BYTES (128 * WS_PITCH * 2)    // 18432

__global__ __launch_bounds__(256)
void mega_kernel(const float* __restrict__ x,
                 const float* __restrict__ W,
                 const float* __restrict__ b,
                 const int*   __restrict__ erow,
                 const int*   __restrict__ ecol,
                 const float* __restrict__ eval,
                 float*       __restrict__ out,
                 const float* __restrict__ alpha,
                 int N, int E) {
    __shared__ __align__(32) unsigned char smem[XS_BYTES + WS_BYTES];
    __shared__ int ws[8];
    __shared__ int sbase;
    __half* Xs = reinterpret_cast<__half*>(smem);
    __half* Ws = reinterpret_cast<__half*>(smem + XS_BYTES);
    float*  Os = reinterpret_cast<float*>(smem);     // overlays Xs exactly

    const int      tid = threadIdx.x;
    const int      bid = blockIdx.x;
    const unsigned nb  = gridDim.x;

    if (bid == 0 && tid == 0) g_ebase = 0;           // consumed after bar0

    // ===== P0: GEMM (all 8 warps) ===========================================
    // Stage W once per block: thread covers one half-row of W.
    {
        const int k = tid >> 1, q = tid & 1;
        const float4* wr = reinterpret_cast<const float4*>(W + (size_t)k * OUT_FT);
        #pragma unroll
        for (int p = 0; p < 8; p++) {
            const int c4 = q * 8 + p;
            const float4 v = __ldg(&wr[c4]);
            __half2 h0 = __floats2half2_rn(v.x, v.y);
            __half2 h1 = __floats2half2_rn(v.z, v.w);
            *reinterpret_cast<__half2*>(&Ws[k * WS_PITCH + c4 * 4])     = h0;
            *reinterpret_cast<__half2*>(&Ws[k * WS_PITCH + c4 * 4 + 2]) = h1;
        }
    }
    __syncthreads();

    const int ntiles = (N + 31) >> 5;
    for (int tile = bid; tile < ntiles; tile += (int)nb) {
        const int row0 = tile * 32;
        // stage X tile: 32 rows x 128 cols, coalesced (8 threads per row)
        {
            const int r = tid >> 3, q = tid & 7;
            const int grow = row0 + r;
            const float4* xr = reinterpret_cast<const float4*>(x + (size_t)grow * IN_FT);
            #pragma unroll
            for (int p = 0; p < 4; p++) {
                const int c4 = q + p * 8;
                float4 v = make_float4(0.f, 0.f, 0.f, 0.f);
                if (grow < N) v = __ldg(&xr[c4]);
                __half2 h0 = __floats2half2_rn(v.x, v.y);
                __half2 h1 = __floats2half2_rn(v.z, v.w);
                *reinterpret_cast<__half2*>(&Xs[r * XS_PITCH + c4 * 4])     = h0;
                *reinterpret_cast<__half2*>(&Xs[r * XS_PITCH + c4 * 4 + 2]) = h1;
            }
        }
        __syncthreads();

        // 8 warps = 2 row-strips x 4 col-tiles of 16x16
        {
            const int w = tid >> 5;
            const int s = w >> 2, nt = w & 3;
            wmma::fragment<wmma::accumulator, 16, 16, 16, float> c;
            wmma::fill_fragment(c, 0.0f);
            #pragma unroll
            for (int k = 0; k < 8; k++) {
                wmma::fragment<wmma::matrix_a, 16, 16, 16, __half, wmma::row_major> a;
                wmma::fragment<wmma::matrix_b, 16, 16, 16, __half, wmma::row_major> bf;
                wmma::load_matrix_sync(a, &Xs[(s * 16) * XS_PITCH + k * 16], XS_PITCH);
                wmma::load_matrix_sync(bf, &Ws[(k * 16) * WS_PITCH + nt * 16], WS_PITCH);
                wmma::mma_sync(c, a, bf, c);
            }
            __syncthreads();   // all warps done reading Xs before Os overwrite
            wmma::store_matrix_sync(&Os[(s * 16) * OS_PITCH + nt * 16], c,
                                    OS_PITCH, wmma::mem_row_major);
        }
        __syncthreads();

        // epilogue: bias + FP32 store. 8 thr/row, 8 floats (2x float4) each.
        {
            const int r = tid >> 3, q = tid & 7;
            const int grow = row0 + r;
            if (grow < N) {
                const float4 v0 = *reinterpret_cast<const float4*>(&Os[r * OS_PITCH + q * 8]);
                const float4 v1 = *reinterpret_cast<const float4*>(&Os[r * OS_PITCH + q * 8 + 4]);
                const float4 b0 = __ldg(reinterpret_cast<const float4*>(b) + q * 2);
                const float4 b1 = __ldg(reinterpret_cast<const float4*>(b) + q * 2 + 1);
                float4 o0, o1;
                o0.x = v0.x + b0.x; o0.y = v0.y + b0.y;
                o0.z = v0.z + b0.z; o0.w = v0.w + b0.w;
                o1.x = v1.x + b1.x; o1.y = v1.y + b1.y;
                o1.z = v1.z + b1.z; o1.w = v1.w + b1.w;
                float* dst = g_h + (size_t)grow * OUT_FT + q * 8;
                *reinterpret_cast<float4*>(dst)     = o0;
                *reinterpret_cast<float4*>(dst + 4) = o1;
            }
        }
        __syncthreads();       // Os fully read before next X staging
    }

    // ===== P1: histogram with rank ==========================================
    const int gtid     = bid * 256 + tid;
    const int gthreads = (int)nb * 256;
    const int nquad    = E >> 2;
    for (int i = gtid; i < nquad; i += gthreads) {
        const int4 r = __ldg(reinterpret_cast<const int4*>(erow) + i);
        const int k0 = atomicAdd(&g_cnt[r.x], 1);
        const int k1 = atomicAdd(&g_cnt[r.y], 1);
        const int k2 = atomicAdd(&g_cnt[r.z], 1);
        const int k3 = atomicAdd(&g_cnt[r.w], 1);
        ushort4 rk;
        rk.x = (unsigned short)k0; rk.y = (unsigned short)k1;
        rk.z = (unsigned short)k2; rk.w = (unsigned short)k3;
        *reinterpret_cast<ushort4*>(g_rank + i * 4) = rk;
    }
    if (gtid == 0) {
        for (int i = nquad * 4; i < E; i++)
            g_rank[i] = (unsigned short)atomicAdd(&g_cnt[erow[i]], 1);
    }

    grid_barrier(0, nb);

    // ===== P2: scan chunks + arrival-order base claim =======================
    {
        const int lane = tid & 31, wid = tid >> 5;
        const int nch = (N + 255) >> 8;
        for (int c = bid; c < nch; c += (int)nb) {
            const int idx = c * 256 + tid;
            const int v = (idx < N) ? g_cnt[idx] : 0;
            int inc = v;
            #pragma unroll
            for (int off = 1; off < 32; off <<= 1) {
                const int t = __shfl_up_sync(0xffffffffu, inc, off);
                if (lane >= off) inc += t;
            }
            if (lane == 31) ws[wid] = inc;
            __syncthreads();
            if (wid == 0) {
                int wv = (lane < 8) ? ws[lane] : 0;
                #pragma unroll
                for (int off = 1; off < 8; off <<= 1) {
                    const int t = __shfl_up_sync(0xffffffffu, wv, off);
                    if (lane >= off) wv += t;
                }
                if (lane < 8) ws[lane] = wv;
                if (lane == 7) sbase = atomicAdd(&g_ebase, wv);
            }
            __syncthreads();
            if (idx < N) {
                const int wofs = (wid > 0) ? ws[wid - 1] : 0;
                g_rowseg[idx] = make_int2(sbase + wofs + inc - v, v);
                g_cnt[idx] = 0;            // restore zero-at-entry invariant
            }
            __syncthreads();               // ws/sbase reuse next chunk
        }
    }

    grid_barrier(1, nb);

    // ===== P3: scatter into dense CSR pairs =================================
    for (int i = gtid; i < nquad; i += gthreads) {
        const int4    r  = __ldg(reinterpret_cast<const int4*>(erow) + i);
        const int4    c  = __ldg(reinterpret_cast<const int4*>(ecol) + i);
        const float4  v  = __ldg(reinterpret_cast<const float4*>(eval) + i);
        const ushort4 rk = *reinterpret_cast<const ushort4*>(g_rank + i * 4);
        g_pairs[g_rowseg[r.x].x + (int)rk.x] = make_int2(c.x, __float_as_int(v.x));
        g_pairs[g_rowseg[r.y].x + (int)rk.y] = make_int2(c.y, __float_as_int(v.y));
        g_pairs[g_rowseg[r.z].x + (int)rk.z] = make_int2(c.z, __float_as_int(v.z));
        g_pairs[g_rowseg[r.w].x + (int)rk.w] = make_int2(c.w, __float_as_int(v.w));
    }
    if (gtid == 0) {
        for (int i = nquad * 4; i < E; i++) {
            const int row = erow[i];
            g_pairs[g_rowseg[row].x + (int)g_rank[i]] =
                make_int2(ecol[i], __float_as_int(eval[i]));
        }
    }

    grid_barrier(2, nb);

    // ===== P4: gather + fused PReLU (fp32 h -> zero conversions) ============
    {
        const int lane = tid & 31;
        const int sub  = lane & 15;    // col group: cols [sub*4, sub*4+4)
        const int half = lane >> 4;    // which edge of a pair
        const int wid  = tid >> 5;
        const float4* __restrict__ hf = reinterpret_cast<const float4*>(g_h);
        const float al = __ldg(alpha);

        for (int row = bid * 8 + wid; row < N; row += (int)nb * 8) {
            const int2 seg  = g_rowseg[row];
            const int  endj = seg.x + seg.y;
            float4 acc = make_float4(0.f, 0.f, 0.f, 0.f);

            int jb = seg.x;
            for (; jb + 7 < endj; jb += 8) {
                const int2 p0 = __ldg(&g_pairs[jb     + half]);
                const int2 p1 = __ldg(&g_pairs[jb + 2 + half]);
                const int2 p2 = __ldg(&g_pairs[jb + 4 + half]);
                const int2 p3 = __ldg(&g_pairs[jb + 6 + half]);
                const float4 q0 = __ldg(&hf[(size_t)p0.x * 16 + sub]);
                const float4 q1 = __ldg(&hf[(size_t)p1.x * 16 + sub]);
                const float4 q2 = __ldg(&hf[(size_t)p2.x * 16 + sub]);
                const float4 q3 = __ldg(&hf[(size_t)p3.x * 16 + sub]);
                const float v0 = __int_as_float(p0.y);
                const float v1 = __int_as_float(p1.y);
                const float v2 = __int_as_float(p2.y);
                const float v3 = __int_as_float(p3.y);
                acc.x = fmaf(v0, q0.x, acc.x); acc.y = fmaf(v0, q0.y, acc.y);
                acc.z = fmaf(v0, q0.z, acc.z); acc.w = fmaf(v0, q0.w, acc.w);
                acc.x = fmaf(v1, q1.x, acc.x); acc.y = fmaf(v1, q1.y, acc.y);
                acc.z = fmaf(v1, q1.z, acc.z); acc.w = fmaf(v1, q1.w, acc.w);
                acc.x = fmaf(v2, q2.x, acc.x); acc.y = fmaf(v2, q2.y, acc.y);
                acc.z = fmaf(v2, q2.z, acc.z); acc.w = fmaf(v2, q2.w, acc.w);
                acc.x = fmaf(v3, q3.x, acc.x); acc.y = fmaf(v3, q3.y, acc.y);
                acc.z = fmaf(v3, q3.z, acc.z); acc.w = fmaf(v3, q3.w, acc.w);
            }
            for (; jb + half < endj; jb += 2) {
                const int2 p = __ldg(&g_pairs[jb + half]);
                const float4 q = __ldg(&hf[(size_t)p.x * 16 + sub]);
                const float v = __int_as_float(p.y);
                acc.x = fmaf(v, q.x, acc.x); acc.y = fmaf(v, q.y, acc.y);
                acc.z = fmaf(v, q.z, acc.z); acc.w = fmaf(v, q.w, acc.w);
            }

            acc.x += __shfl_xor_sync(0xffffffffu, acc.x, 16);
            acc.y += __shfl_xor_sync(0xffffffffu, acc.y, 16);
            acc.z += __shfl_xor_sync(0xffffffffu, acc.z, 16);
            acc.w += __shfl_xor_sync(0xffffffffu, acc.w, 16);

            if (half == 0) {
                float4 o;
                o.x = acc.x >= 0.f ? acc.x : al * acc.x;
                o.y = acc.y >= 0.f ? acc.y : al * acc.y;
                o.z = acc.z >= 0.f ? acc.z : al * acc.z;
                o.w = acc.w >= 0.f ? acc.w : al * acc.w;
                reinterpret_cast<float4*>(out)[(size_t)row * 16 + sub] = o;
            }
        }
    }
}

// ---------------------------------------------------------------------------
// Launch. Inputs: x, W, b, alpha, edge_row, edge_col, edge_val
// One persistent kernel; grid sized for guaranteed co-residency.
// ---------------------------------------------------------------------------
extern "C" void kernel_launch(void* const* d_in, const int* in_sizes, int n_in,
                              void* d_out, int out_size) {
    const float* x     = (const float*)d_in[0];
    const float* W     = (const float*)d_in[1];
    const float* b     = (const float*)d_in[2];
    const float* alpha = (const float*)d_in[3];
    const int*   erow  = (const int*)  d_in[4];
    const int*   ecol  = (const int*)  d_in[5];
    const float* eval  = (const float*)d_in[6];

    const int N = in_sizes[0] / IN_FT;
    const int E = in_sizes[4];
    float* out = (float*)d_out;

    int dev = 0, smc = 0, bpm = 0;
    cudaGetDevice(&dev);
    cudaDeviceGetAttribute(&smc, cudaDevAttrMultiProcessorCount, dev);
    cudaOccupancyMaxActiveBlocksPerMultiprocessor(&bpm, mega_kernel, 256, 0);
    if (bpm < 1) bpm = 1;
    int grid = bpm * smc;
    if (grid < 1) grid = 1;

    mega_kernel<<<grid, 256>>>(x, W, b, erow, ecol, eval, out, alpha, N, E);
}

// round 16
// speedup vs baseline: 1.0581x; 1.0581x over previous
#include <cuda_runtime.h>
#include <cuda_fp16.h>
#include <mma.h>
#include <cstdint>

using namespace nvcuda;

// ---------------------------------------------------------------------------
// GCN layer on GB300 (sm_103a): ONE persistent kernel, software grid barriers.
// Architecture = R12 (best measured, 92.6us; fp16 h) + two latency surgeries:
//   - P3 stores prescaled cols (col<<4) so P4's h address is hh[p.x + sub]
//   - P4 prefetches the next row's {start,count} before processing current
//   P0 gemm   : h = xW + b, wmma HMMA (fp16 in, fp32 acc), fp16 h out
//   P1 hist   : per-row counts; atomicAdd return = rank
//   -- bar0 --
//   P2 scan   : per-256 chunk exclusive scan + arrival-order base claim
//   -- bar1 --
//   P3 scatter: dense CSR pairs (no atomics), prescaled cols
//   -- bar2 --
//   P4 gather : warp-per-row SpMM + fused PReLU (fp16 h, half-warp edges)
// ---------------------------------------------------------------------------

#define IN_FT   128
#define OUT_FT  64
#define N_CAP   131072
#define E_CAP   1605632

static __device__ __half         g_h[(size_t)N_CAP * OUT_FT];  // 12.8 MB
static __device__ int            g_cnt[N_CAP + 2];   // zero at entry (P2 resets)
static __device__ int2           g_rowseg[N_CAP];    // {start, count}
static __device__ int            g_ebase;            // arrival-order allocator
static __device__ unsigned short g_rank[E_CAP];
static __device__ int2           g_pairs[E_CAP];     // (col<<4, val bits)
static __device__ unsigned       g_barCnt[4];        // monotonic
static __device__ unsigned       g_barRel[4];        // monotonic

// ---- epoch grid barrier (monotonic; safe across graph replays) -------------
__device__ __forceinline__ void grid_barrier(int id, unsigned nb) {
    __syncthreads();
    if (threadIdx.x == 0) {
        __threadfence();
        const unsigned t     = atomicAdd(&g_barCnt[id], 1u);
        const unsigned epoch = t / nb + 1u;
        if ((t % nb) == nb - 1u) atomicAdd(&g_barRel[id], 1u);
        while (*((volatile unsigned*)&g_barRel[id]) < epoch) __nanosleep(64);
    }
    __syncthreads();
}

#define XS_PITCH 136
#define WS_PITCH 72
#define OS_PITCH 68
#define XS_BYTES (32 * XS_PITCH * 2)     // 8704 (== 32*68*4; Os overlays Xs)
#define WS_BYTES (128 * WS_PITCH * 2)    // 18432

__global__ __launch_bounds__(256)
void mega_kernel(const float* __restrict__ x,
                 const float* __restrict__ W,
                 const float* __restrict__ b,
                 const int*   __restrict__ erow,
                 const int*   __restrict__ ecol,
                 const float* __restrict__ eval,
                 float*       __restrict__ out,
                 const float* __restrict__ alpha,
                 int N, int E) {
    __shared__ __align__(32) unsigned char smem[XS_BYTES + WS_BYTES];
    __shared__ int ws[8];
    __shared__ int sbase;
    __half* Xs = reinterpret_cast<__half*>(smem);
    __half* Ws = reinterpret_cast<__half*>(smem + XS_BYTES);
    float*  Os = reinterpret_cast<float*>(smem);     // overlays Xs exactly

    const int      tid = threadIdx.x;
    const int      bid = blockIdx.x;
    const unsigned nb  = gridDim.x;

    if (bid == 0 && tid == 0) g_ebase = 0;           // consumed after bar0

    // ===== P0: GEMM (all 8 warps) ===========================================
    {
        const int k = tid >> 1, q = tid & 1;
        const float4* wr = reinterpret_cast<const float4*>(W + (size_t)k * OUT_FT);
        #pragma unroll
        for (int p = 0; p < 8; p++) {
            const int c4 = q * 8 + p;
            const float4 v = __ldg(&wr[c4]);
            __half2 h0 = __floats2half2_rn(v.x, v.y);
            __half2 h1 = __floats2half2_rn(v.z, v.w);
            *reinterpret_cast<__half2*>(&Ws[k * WS_PITCH + c4 * 4])     = h0;
            *reinterpret_cast<__half2*>(&Ws[k * WS_PITCH + c4 * 4 + 2]) = h1;
        }
    }
    __syncthreads();

    const int ntiles = (N + 31) >> 5;
    for (int tile = bid; tile < ntiles; tile += (int)nb) {
        const int row0 = tile * 32;
        // stage X tile: 32 rows x 128 cols, coalesced (8 threads per row)
        {
            const int r = tid >> 3, q = tid & 7;
            const int grow = row0 + r;
            const float4* xr = reinterpret_cast<const float4*>(x + (size_t)grow * IN_FT);
            #pragma unroll
            for (int p = 0; p < 4; p++) {
                const int c4 = q + p * 8;
                float4 v = make_float4(0.f, 0.f, 0.f, 0.f);
                if (grow < N) v = __ldg(&xr[c4]);
                __half2 h0 = __floats2half2_rn(v.x, v.y);
                __half2 h1 = __floats2half2_rn(v.z, v.w);
                *reinterpret_cast<__half2*>(&Xs[r * XS_PITCH + c4 * 4])     = h0;
                *reinterpret_cast<__half2*>(&Xs[r * XS_PITCH + c4 * 4 + 2]) = h1;
            }
        }
        __syncthreads();

        // 8 warps = 2 row-strips x 4 col-tiles of 16x16
        {
            const int w = tid >> 5;
            const int s = w >> 2, nt = w & 3;
            wmma::fragment<wmma::accumulator, 16, 16, 16, float> c;
            wmma::fill_fragment(c, 0.0f);
            #pragma unroll
            for (int k = 0; k < 8; k++) {
                wmma::fragment<wmma::matrix_a, 16, 16, 16, __half, wmma::row_major> a;
                wmma::fragment<wmma::matrix_b, 16, 16, 16, __half, wmma::row_major> bf;
                wmma::load_matrix_sync(a, &Xs[(s * 16) * XS_PITCH + k * 16], XS_PITCH);
                wmma::load_matrix_sync(bf, &Ws[(k * 16) * WS_PITCH + nt * 16], WS_PITCH);
                wmma::mma_sync(c, a, bf, c);
            }
            __syncthreads();   // all warps done reading Xs before Os overwrite
            wmma::store_matrix_sync(&Os[(s * 16) * OS_PITCH + nt * 16], c,
                                    OS_PITCH, wmma::mem_row_major);
        }
        __syncthreads();

        // epilogue: bias + fp16 pack, one 16B store per thread
        {
            const int r = tid >> 3, q = tid & 7;
            const int grow = row0 + r;
            if (grow < N) {
                const float4 v0 = *reinterpret_cast<const float4*>(&Os[r * OS_PITCH + q * 8]);
                const float4 v1 = *reinterpret_cast<const float4*>(&Os[r * OS_PITCH + q * 8 + 4]);
                const float4 b0 = __ldg(reinterpret_cast<const float4*>(b) + q * 2);
                const float4 b1 = __ldg(reinterpret_cast<const float4*>(b) + q * 2 + 1);
                __half2 h0 = __floats2half2_rn(v0.x + b0.x, v0.y + b0.y);
                __half2 h1 = __floats2half2_rn(v0.z + b0.z, v0.w + b0.w);
                __half2 h2 = __floats2half2_rn(v1.x + b1.x, v1.y + b1.y);
                __half2 h3 = __floats2half2_rn(v1.z + b1.z, v1.w + b1.w);
                uint4 o;
                o.x = *reinterpret_cast<unsigned*>(&h0);
                o.y = *reinterpret_cast<unsigned*>(&h1);
                o.z = *reinterpret_cast<unsigned*>(&h2);
                o.w = *reinterpret_cast<unsigned*>(&h3);
                *reinterpret_cast<uint4*>(g_h + (size_t)grow * OUT_FT + q * 8) = o;
            }
        }
        __syncthreads();       // Os fully read before next X staging
    }

    // ===== P1: histogram with rank ==========================================
    const int gtid     = bid * 256 + tid;
    const int gthreads = (int)nb * 256;
    const int nquad    = E >> 2;
    for (int i = gtid; i < nquad; i += gthreads) {
        const int4 r = __ldg(reinterpret_cast<const int4*>(erow) + i);
        const int k0 = atomicAdd(&g_cnt[r.x], 1);
        const int k1 = atomicAdd(&g_cnt[r.y], 1);
        const int k2 = atomicAdd(&g_cnt[r.z], 1);
        const int k3 = atomicAdd(&g_cnt[r.w], 1);
        ushort4 rk;
        rk.x = (unsigned short)k0; rk.y = (unsigned short)k1;
        rk.z = (unsigned short)k2; rk.w = (unsigned short)k3;
        *reinterpret_cast<ushort4*>(g_rank + i * 4) = rk;
    }
    if (gtid == 0) {
        for (int i = nquad * 4; i < E; i++)
            g_rank[i] = (unsigned short)atomicAdd(&g_cnt[erow[i]], 1);
    }

    grid_barrier(0, nb);

    // ===== P2: scan chunks + arrival-order base claim =======================
    {
        const int lane = tid & 31, wid = tid >> 5;
        const int nch = (N + 255) >> 8;
        for (int c = bid; c < nch; c += (int)nb) {
            const int idx = c * 256 + tid;
            const int v = (idx < N) ? g_cnt[idx] : 0;
            int inc = v;
            #pragma unroll
            for (int off = 1; off < 32; off <<= 1) {
                const int t = __shfl_up_sync(0xffffffffu, inc, off);
                if (lane >= off) inc += t;
            }
            if (lane == 31) ws[wid] = inc;
            __syncthreads();
            if (wid == 0) {
                int wv = (lane < 8) ? ws[lane] : 0;
                #pragma unroll
                for (int off = 1; off < 8; off <<= 1) {
                    const int t = __shfl_up_sync(0xffffffffu, wv, off);
                    if (lane >= off) wv += t;
                }
                if (lane < 8) ws[lane] = wv;
                if (lane == 7) sbase = atomicAdd(&g_ebase, wv);
            }
            __syncthreads();
            if (idx < N) {
                const int wofs = (wid > 0) ? ws[wid - 1] : 0;
                g_rowseg[idx] = make_int2(sbase + wofs + inc - v, v);
                g_cnt[idx] = 0;            // restore zero-at-entry invariant
            }
            __syncthreads();               // ws/sbase reuse next chunk
        }
    }

    grid_barrier(1, nb);

    // ===== P3: scatter into dense CSR pairs (cols prescaled by 16) =========
    for (int i = gtid; i < nquad; i += gthreads) {
        const int4    r  = __ldg(reinterpret_cast<const int4*>(erow) + i);
        const int4    c  = __ldg(reinterpret_cast<const int4*>(ecol) + i);
        const float4  v  = __ldg(reinterpret_cast<const float4*>(eval) + i);
        const ushort4 rk = *reinterpret_cast<const ushort4*>(g_rank + i * 4);
        g_pairs[g_rowseg[r.x].x + (int)rk.x] = make_int2(c.x << 4, __float_as_int(v.x));
        g_pairs[g_rowseg[r.y].x + (int)rk.y] = make_int2(c.y << 4, __float_as_int(v.y));
        g_pairs[g_rowseg[r.z].x + (int)rk.z] = make_int2(c.z << 4, __float_as_int(v.z));
        g_pairs[g_rowseg[r.w].x + (int)rk.w] = make_int2(c.w << 4, __float_as_int(v.w));
    }
    if (gtid == 0) {
        for (int i = nquad * 4; i < E; i++) {
            const int row = erow[i];
            g_pairs[g_rowseg[row].x + (int)g_rank[i]] =
                make_int2(ecol[i] << 4, __float_as_int(eval[i]));
        }
    }

    grid_barrier(2, nb);

    // ===== P4: gather + fused PReLU (fp16 h; next-row seg prefetch) =========
    {
        const int lane = tid & 31;
        const int sub  = lane & 15;    // col group: cols [sub*4, sub*4+4)
        const int half = lane >> 4;    // which edge of a pair
        const int wid  = tid >> 5;
        const int rstep = (int)nb * 8;
        const uint2* __restrict__ hh = reinterpret_cast<const uint2*>(g_h);
        const float al = __ldg(alpha);

        int row = bid * 8 + wid;
        int2 seg = make_int2(0, 0);
        if (row < N) seg = g_rowseg[row];

        while (row < N) {
            // prefetch next row's segment before touching this row's edges
            const int nrow = row + rstep;
            int2 nseg = make_int2(0, 0);
            if (nrow < N) nseg = g_rowseg[nrow];

            const int endj = seg.x + seg.y;
            float4 acc = make_float4(0.f, 0.f, 0.f, 0.f);

            int jb = seg.x;
            for (; jb + 7 < endj; jb += 8) {
                const int2 p0 = __ldg(&g_pairs[jb     + half]);
                const int2 p1 = __ldg(&g_pairs[jb + 2 + half]);
                const int2 p2 = __ldg(&g_pairs[jb + 4 + half]);
                const int2 p3 = __ldg(&g_pairs[jb + 6 + half]);
                const uint2 q0 = __ldg(&hh[p0.x + sub]);
                const uint2 q1 = __ldg(&hh[p1.x + sub]);
                const uint2 q2 = __ldg(&hh[p2.x + sub]);
                const uint2 q3 = __ldg(&hh[p3.x + sub]);
                const float v0 = __int_as_float(p0.y);
                const float v1 = __int_as_float(p1.y);
                const float v2 = __int_as_float(p2.y);
                const float v3 = __int_as_float(p3.y);

                float2 a, b2;
                a  = __half22float2(*reinterpret_cast<const __half2*>(&q0.x));
                b2 = __half22float2(*reinterpret_cast<const __half2*>(&q0.y));
                acc.x = fmaf(v0, a.x, acc.x);  acc.y = fmaf(v0, a.y, acc.y);
                acc.z = fmaf(v0, b2.x, acc.z); acc.w = fmaf(v0, b2.y, acc.w);
                a  = __half22float2(*reinterpret_cast<const __half2*>(&q1.x));
                b2 = __half22float2(*reinterpret_cast<const __half2*>(&q1.y));
                acc.x = fmaf(v1, a.x, acc.x);  acc.y = fmaf(v1, a.y, acc.y);
                acc.z = fmaf(v1, b2.x, acc.z); acc.w = fmaf(v1, b2.y, acc.w);
                a  = __half22float2(*reinterpret_cast<const __half2*>(&q2.x));
                b2 = __half22float2(*reinterpret_cast<const __half2*>(&q2.y));
                acc.x = fmaf(v2, a.x, acc.x);  acc.y = fmaf(v2, a.y, acc.y);
                acc.z = fmaf(v2, b2.x, acc.z); acc.w = fmaf(v2, b2.y, acc.w);
                a  = __half22float2(*reinterpret_cast<const __half2*>(&q3.x));
                b2 = __half22float2(*reinterpret_cast<const __half2*>(&q3.y));
                acc.x = fmaf(v3, a.x, acc.x);  acc.y = fmaf(v3, a.y, acc.y);
                acc.z = fmaf(v3, b2.x, acc.z); acc.w = fmaf(v3, b2.y, acc.w);
            }
            for (; jb + half < endj; jb += 2) {
                const int2 p = __ldg(&g_pairs[jb + half]);
                const uint2 q = __ldg(&hh[p.x + sub]);
                const float v = __int_as_float(p.y);
                const float2 a  = __half22float2(*reinterpret_cast<const __half2*>(&q.x));
                const float2 b2 = __half22float2(*reinterpret_cast<const __half2*>(&q.y));
                acc.x = fmaf(v, a.x, acc.x);  acc.y = fmaf(v, a.y, acc.y);
                acc.z = fmaf(v, b2.x, acc.z); acc.w = fmaf(v, b2.y, acc.w);
            }

            acc.x += __shfl_xor_sync(0xffffffffu, acc.x, 16);
            acc.y += __shfl_xor_sync(0xffffffffu, acc.y, 16);
            acc.z += __shfl_xor_sync(0xffffffffu, acc.z, 16);
            acc.w += __shfl_xor_sync(0xffffffffu, acc.w, 16);

            if (half == 0) {
                float4 o;
                o.x = acc.x >= 0.f ? acc.x : al * acc.x;
                o.y = acc.y >= 0.f ? acc.y : al * acc.y;
                o.z = acc.z >= 0.f ? acc.z : al * acc.z;
                o.w = acc.w >= 0.f ? acc.w : al * acc.w;
                reinterpret_cast<float4*>(out)[(size_t)row * 16 + sub] = o;
            }

            row = nrow;
            seg = nseg;
        }
    }
}

// ---------------------------------------------------------------------------
// Launch. Inputs: x, W, b, alpha, edge_row, edge_col, edge_val
// One persistent kernel; grid sized for guaranteed co-residency.
// ---------------------------------------------------------------------------
extern "C" void kernel_launch(void* const* d_in, const int* in_sizes, int n_in,
                              void* d_out, int out_size) {
    const float* x     = (const float*)d_in[0];
    const float* W     = (const float*)d_in[1];
    const float* b     = (const float*)d_in[2];
    const float* alpha = (const float*)d_in[3];
    const int*   erow  = (const int*)  d_in[4];
    const int*   ecol  = (const int*)  d_in[5];
    const float* eval  = (const float*)d_in[6];

    const int N = in_sizes[0] / IN_FT;
    const int E = in_sizes[4];
    float* out = (float*)d_out;

    int dev = 0, smc = 0, bpm = 0;
    cudaGetDevice(&dev);
    cudaDeviceGetAttribute(&smc, cudaDevAttrMultiProcessorCount, dev);
    cudaOccupancyMaxActiveBlocksPerMultiprocessor(&bpm, mega_kernel, 256, 0);
    if (bpm < 1) bpm = 1;
    int grid = bpm * smc;
    if (grid < 1) grid = 1;

    mega_kernel<<<grid, 256>>>(x, W, b, erow, ecol, eval, out, alpha, N, E);
}